// round 11
// baseline (speedup 1.0000x reference)
#include <cuda_runtime.h>

#define KNN 16
#define NPTS 8192
#define DIMS 64
#define TILE 128
#define NTHR 512
#define APITCH 66     // ull per d-row of A: 64 pairs + 2 pad (even -> 16B-aligned LDS.128)
#define BPITCH 132    // floats per d-row of B (mult of 4 for cp.async 16B)

__device__ float g_xT[2][DIMS][NPTS];   // transposed points
__device__ float g_nrm[2][NPTS];        // squared norms

#define FMA2(acc, a, b) \
    asm("fma.rn.f32x2 %0, %1, %2, %0;" : "+l"(acc) : "l"(a), "l"(b))
#define CP_ASYNC16(smem_u32, gptr) \
    asm volatile("cp.async.ca.shared.global [%0], [%1], 16;" \
                 :: "r"(smem_u32), "l"(gptr))
#define CP_COMMIT()  asm volatile("cp.async.commit_group;")
#define CP_WAIT0()   asm volatile("cp.async.wait_group 0;" ::: "memory")

// lexicographic (dist, idx) sorted insert into a 16-entry list
__device__ __forceinline__ void insert_one(float* kds, int* kis, int base,
                                           float d, int idx) {
    const float tail = kds[base + KNN - 1];
    const int   tix  = kis[base + KNN - 1];
    if (d < tail || (d == tail && idx < tix)) {
        int j = KNN - 1;
        while (j > 0 && (kds[base + j - 1] > d ||
                         (kds[base + j - 1] == d && kis[base + j - 1] > idx))) {
            kds[base + j] = kds[base + j - 1];
            kis[base + j] = kis[base + j - 1];
            j--;
        }
        kds[base + j] = d;
        kis[base + j] = idx;
    }
}

// ---- pre-kernel: tiled transpose + norms (one-time) ----
__global__ __launch_bounds__(256, 1)
void pre_kernel(const float* __restrict__ x) {
    __shared__ float s[TILE][DIMS + 1];
    const int b = blockIdx.y, n0 = blockIdx.x * TILE, tid = threadIdx.x;
    const float* xb = x + (size_t)b * NPTS * DIMS;

    for (int i = tid; i < TILE * (DIMS / 4); i += 256) {
        const int r = i >> 4, d4 = i & 15;
        float4 v = *(const float4*)&xb[(size_t)(n0 + r) * DIMS + 4 * d4];
        s[r][4 * d4 + 0] = v.x; s[r][4 * d4 + 1] = v.y;
        s[r][4 * d4 + 2] = v.z; s[r][4 * d4 + 3] = v.w;
    }
    __syncthreads();
    if (tid < TILE) {
        float sum = 0.f;
        #pragma unroll
        for (int d = 0; d < DIMS; d++) sum = fmaf(s[tid][d], s[tid][d], sum);
        g_nrm[b][n0 + tid] = sum;
    }
    for (int i = tid; i < DIMS * TILE; i += 256) {
        const int d = i >> 7, c = i & 127;
        g_xT[b][d][n0 + c] = s[c][d];
    }
}

// ---- main kernel: fused GEMM + race-free privatized top-k ----
__global__ __launch_bounds__(NTHR, 1)
void knn6(const float* __restrict__ x, float* __restrict__ out) {
    extern __shared__ unsigned long long smem_u64[];
    unsigned long long* AsP = smem_u64;                    // [64][APITCH] ull
    float* Bs0  = (float*)(AsP + DIMS * APITCH);           // [64][BPITCH]
    float* Bs1  = Bs0 + DIMS * BPITCH;                     // [64][BPITCH]
    float* kds  = Bs1 + DIMS * BPITCH;                     // [128][4][16]
    int*   kis  = (int*)(kds + TILE * 4 * KNN);            // [128][4][16]
    float* snrm = (float*)(kis + TILE * 4 * KNN);          // [8192]
    float* AsPf = (float*)AsP;

    const int tid    = threadIdx.x;
    const int lane   = tid & 31;
    const int warp   = tid >> 5;       // 0..15
    const int wy     = lane >> 3;      // 0..3
    const int wx     = lane & 7;       // 0..7
    const int warp_y = warp >> 2;      // 0..3
    const int warp_x = warp & 3;       // 0..3
    const int batch  = blockIdx.y;
    const int row0   = blockIdx.x * TILE;

    const int pg    = 4 * warp_y + wy;      // pair-group 0..15; rows 8*pg..8*pg+7
    const int cbase = 32 * warp_x + wx;     // cols: cbase + 8*n, n=0..3

    const float INF = __int_as_float(0x7f800000);

    // init private lists + stage all norms in smem
    for (int i = tid; i < TILE * 4 * KNN; i += NTHR) { kds[i] = INF; kis[i] = 0; }
    for (int i = tid; i < NPTS; i += NTHR) snrm[i] = g_nrm[batch][i];

    // A tile: AsPf[d][r] (coalesced LDG, conflict-free STS)
    for (int i = tid; i < DIMS * TILE; i += NTHR) {
        const int d = i >> 7, r = i & 127;
        AsPf[d * (2 * APITCH) + r] = g_xT[batch][d][row0 + r];
    }

    // prefetch B(0)
    for (int k = 0; k < 4; k++) {
        const int idx = tid + k * NTHR;          // 64 d x 32 c4
        const int d = idx >> 5, c4 = idx & 31;
        CP_ASYNC16((unsigned)__cvta_generic_to_shared(&Bs0[d * BPITCH + 4 * c4]),
                   &g_xT[batch][d][4 * c4]);
    }
    CP_COMMIT();

    __syncthreads();   // lists, snrm, A visible

    // per-thread row norms + cached kth per owned row (stale-conservative)
    float sa[8], kth[8];
    #pragma unroll
    for (int k = 0; k < 8; k++) { sa[k] = snrm[row0 + 8 * pg + k]; kth[k] = INF; }

    float* cur = Bs0;
    float* nxt = Bs1;

    for (int t = 0; t < NPTS / TILE; t++) {
        const int col0 = t * TILE;

        CP_WAIT0();
        __syncthreads();     // B(t) visible; everyone done with prev cur

        if (t + 1 < NPTS / TILE) {
            const int ncol0 = col0 + TILE;
            for (int k = 0; k < 4; k++) {
                const int idx = tid + k * NTHR;
                const int d = idx >> 5, c4 = idx & 31;
                CP_ASYNC16((unsigned)__cvta_generic_to_shared(&nxt[d * BPITCH + 4 * c4]),
                           &g_xT[batch][d][ncol0 + 4 * c4]);
            }
            CP_COMMIT();
        }

        // candidate norms (broadcast LDS)
        float sb[4];
        #pragma unroll
        for (int n = 0; n < 4; n++) sb[n] = snrm[col0 + cbase + 8 * n];

        // ---- GEMM: M-packed f32x2, 4 consecutive pairs x 4 cols ----
        unsigned long long acc2[4][4];
        #pragma unroll
        for (int p = 0; p < 4; p++)
            #pragma unroll
            for (int n = 0; n < 4; n++) acc2[p][n] = 0ull;

        const unsigned long long* aptr = AsP + 4 * pg;
        const float* bptr = cur + cbase;

        #pragma unroll 8
        for (int d = 0; d < DIMS; d++) {
            ulonglong2 av0 = *(const ulonglong2*)(aptr + d * APITCH);       // pairs 0,1
            ulonglong2 av1 = *(const ulonglong2*)(aptr + d * APITCH + 2);   // pairs 2,3
            unsigned long long a2[4] = {av0.x, av0.y, av1.x, av1.y};
            unsigned long long bd[4];
            #pragma unroll
            for (int n = 0; n < 4; n++) {
                const float bv = bptr[d * BPITCH + 8 * n];
                asm("mov.b64 %0, {%1, %1};" : "=l"(bd[n]) : "f"(bv));
            }
            #pragma unroll
            for (int p = 0; p < 4; p++)
                #pragma unroll
                for (int n = 0; n < 4; n++) FMA2(acc2[p][n], a2[p], bd[n]);
        }

        // ---- fast filter: register-only threshold check ----
        bool need = false;
        #pragma unroll
        for (int p = 0; p < 4; p++) {
            #pragma unroll
            for (int n = 0; n < 4; n++) {
                float lo, hi;
                asm("mov.b64 {%0, %1}, %2;" : "=f"(lo), "=f"(hi) : "l"(acc2[p][n]));
                const float d0 = (sa[2 * p]     - 2.f * lo) + sb[n];
                const float d1 = (sa[2 * p + 1] - 2.f * hi) + sb[n];
                need |= (d0 <= kth[2 * p]);
                need |= (d1 <= kth[2 * p + 1]);
            }
        }

        // ---- rare path: turn-serialized inserts (8 lanes share each list) ----
        const unsigned need_mask = __ballot_sync(0xffffffffu, need);
        if (need_mask) {
            #pragma unroll
            for (int turn = 0; turn < 8; turn++) {
                if (need_mask & (0x01010101u << turn)) {   // warp-uniform guard
                    if (wx == turn && need) {
                        #pragma unroll
                        for (int p = 0; p < 4; p++) {
                            #pragma unroll
                            for (int n = 0; n < 4; n++) {
                                float lo, hi;
                                asm("mov.b64 {%0, %1}, %2;"
                                    : "=f"(lo), "=f"(hi) : "l"(acc2[p][n]));
                                const int cg = col0 + cbase + 8 * n;
                                const float d0 = (sa[2 * p]     - 2.f * lo) + sb[n];
                                const float d1 = (sa[2 * p + 1] - 2.f * hi) + sb[n];
                                insert_one(kds, kis,
                                           ((8 * pg + 2 * p) * 4 + warp_x) * KNN, d0, cg);
                                insert_one(kds, kis,
                                           ((8 * pg + 2 * p + 1) * 4 + warp_x) * KNN, d1, cg);
                            }
                        }
                    }
                    __syncwarp();
                }
            }
            // refresh cached thresholds from settled lists (broadcast LDS)
            #pragma unroll
            for (int k = 0; k < 8; k++)
                kth[k] = kds[((8 * pg + k) * 4 + warp_x) * KNN + KNN - 1];
        }

        float* tmp = cur; cur = nxt; nxt = tmp;
        // loop-top barrier is the only per-tile barrier
    }

    __syncthreads();   // all private lists final

    // ---- merge 4 sorted sub-lists per row (lexicographic); write output ----
    if (tid < TILE) {
        float* out_nn = out;
        float* out_c  = out + 2 * NPTS * KNN;
        const int grow = row0 + tid;
        const size_t obase = ((size_t)batch * NPTS + grow) * KNN;

        int ptr4[4] = {0, 0, 0, 0};
        #pragma unroll
        for (int j = 0; j < KNN; j++) {
            float best = INF; int bidx = 0x7fffffff; int bl = 0;
            #pragma unroll
            for (int l = 0; l < 4; l++) {
                if (ptr4[l] < KNN) {
                    const int bs = (tid * 4 + l) * KNN + ptr4[l];
                    const float dv = kds[bs];
                    const int   iv = kis[bs];
                    if (dv < best || (dv == best && iv < bidx)) {
                        best = dv; bidx = iv; bl = l;
                    }
                }
            }
            ptr4[bl]++;
            out_nn[obase + j] = (float)bidx;
            out_c [obase + j] = (float)grow;
        }
    }
}

extern "C" void kernel_launch(void* const* d_in, const int* in_sizes, int n_in,
                              void* d_out, int out_size) {
    const float* x = (const float*)d_in[0];
    float* out = (float*)d_out;

    const size_t smem_bytes =
        (size_t)DIMS * APITCH * 8 +              // AsP   (33,792)
        (size_t)2 * DIMS * BPITCH * 4 +          // Bs0/1 (67,584)
        (size_t)TILE * 4 * KNN * 4 * 2 +         // kds+kis (65,536)
        (size_t)NPTS * 4;                        // snrm  (32,768)  => 199,680

    cudaFuncSetAttribute(knn6,
                         cudaFuncAttributeMaxDynamicSharedMemorySize,
                         (int)smem_bytes);

    dim3 pgrid(NPTS / TILE, 2);
    pre_kernel<<<pgrid, 256>>>(x);

    dim3 grid(NPTS / TILE, 2);
    knn6<<<grid, NTHR, smem_bytes>>>(x, out);
}

// round 13
// speedup vs baseline: 17.5148x; 17.5148x over previous
#include <cuda_runtime.h>

#define KNN 16
#define NPTS 8192
#define DIMS 64
#define TILE 128
#define NTHR 512
#define APITCH 66     // ull per d-row of A: 64 pairs + 2 pad (16B-aligned LDS.128)
#define BPITCH 132    // floats per d-row of B (mult of 4 for cp.async 16B)
#define DST 132       // Ds stride: epilogue bank = 8*wy+wx (+const) -> conflict-free

__device__ float g_xT[2][DIMS][NPTS];   // transposed points
__device__ float g_nrm[2][NPTS];        // squared norms

#define FMA2(acc, a, b) \
    asm("fma.rn.f32x2 %0, %1, %2, %0;" : "+l"(acc) : "l"(a), "l"(b))
#define CP_ASYNC16(smem_u32, gptr) \
    asm volatile("cp.async.ca.shared.global [%0], [%1], 16;" \
                 :: "r"(smem_u32), "l"(gptr))
#define CP_COMMIT()  asm volatile("cp.async.commit_group;")
#define CP_WAIT0()   asm volatile("cp.async.wait_group 0;" ::: "memory")

// ---- pre-kernel: tiled transpose + norms (one-time) ----
__global__ __launch_bounds__(256, 1)
void pre_kernel(const float* __restrict__ x) {
    __shared__ float s[TILE][DIMS + 1];
    const int b = blockIdx.y, n0 = blockIdx.x * TILE, tid = threadIdx.x;
    const float* xb = x + (size_t)b * NPTS * DIMS;

    for (int i = tid; i < TILE * (DIMS / 4); i += 256) {
        const int r = i >> 4, d4 = i & 15;
        float4 v = *(const float4*)&xb[(size_t)(n0 + r) * DIMS + 4 * d4];
        s[r][4 * d4 + 0] = v.x; s[r][4 * d4 + 1] = v.y;
        s[r][4 * d4 + 2] = v.z; s[r][4 * d4 + 3] = v.w;
    }
    __syncthreads();
    if (tid < TILE) {
        float sum = 0.f;
        #pragma unroll
        for (int d = 0; d < DIMS; d++) sum = fmaf(s[tid][d], s[tid][d], sum);
        g_nrm[b][n0 + tid] = sum;
    }
    for (int i = tid; i < DIMS * TILE; i += 256) {
        const int d = i >> 7, c = i & 127;
        g_xT[b][d][n0 + c] = s[c][d];
    }
}

// ---- main kernel: round-9 GEMM (fixed base ptr) + fully-parallel selection ----
__global__ __launch_bounds__(NTHR, 1)
void knn8(const float* __restrict__ x, float* __restrict__ out) {
    extern __shared__ unsigned long long smem_u64[];
    unsigned long long* AsP = smem_u64;                    // [64][APITCH] ull (33,792 B)
    float* Bs0 = (float*)(AsP + DIMS * APITCH);            // [64][BPITCH]   (33,792 B)
    float* Bs1 = Bs0 + DIMS * BPITCH;                      // [64][BPITCH]   (33,792 B)
    float* Ds  = Bs1 + DIMS * BPITCH;                      // [128][DST]     (67,584 B)
    float* kds = Ds + TILE * DST;                          // [128][4][16]   (32,768 B)
    unsigned short* kis = (unsigned short*)(kds + TILE * 4 * KNN); // [128][4][16]
    float* AsPf = (float*)AsP;

    const int tid    = threadIdx.x;
    const int lane   = tid & 31;
    const int warp   = tid >> 5;       // 0..15
    const int wy     = lane >> 3;      // 0..3
    const int wx     = lane & 7;       // 0..7
    const int warp_y = warp >> 2;      // 0..3
    const int warp_x = warp & 3;       // 0..3
    const int batch  = blockIdx.y;
    const int row0   = blockIdx.x * TILE;

    const float INF = __int_as_float(0x7f800000);

    // private sub-lists: thread (srow, sq) owns list [srow][sq]
    const int srow = tid >> 2;         // 0..127
    const int sq   = tid & 3;          // 0..3
    const int sbase = (srow * 4 + sq) * KNN;
    #pragma unroll
    for (int j = 0; j < KNN; j++) { kds[sbase + j] = INF; kis[sbase + j] = 0; }
    float kth = INF;

    // A tile: AsPf[d][r] = xT[b][d][row0+r]  (coalesced LDG, conflict-free STS)
    for (int i = tid; i < DIMS * TILE; i += NTHR) {
        const int d = i >> 7, r = i & 127;
        AsPf[d * (2 * APITCH) + r] = g_xT[batch][d][row0 + r];
    }

    const int prbase = 16 * warp_y + wy;   // GEMM row-pairs: prbase + 4*p
    const int cbase  = 32 * warp_x + wx;   // GEMM cols:      cbase + 8*n

    // per-thread GEMM row norms
    float sa0[4], sa1[4];
    #pragma unroll
    for (int p = 0; p < 4; p++) {
        const int r0 = 2 * (prbase + 4 * p);
        sa0[p] = g_nrm[batch][row0 + r0];
        sa1[p] = g_nrm[batch][row0 + r0 + 1];
    }

    // prefetch B(0)
    for (int k = 0; k < 4; k++) {
        const int idx = tid + k * NTHR;          // 64 d x 32 c4
        const int d = idx >> 5, c4 = idx & 31;
        CP_ASYNC16((unsigned)__cvta_generic_to_shared(&Bs0[d * BPITCH + 4 * c4]),
                   &g_xT[batch][d][4 * c4]);
    }
    CP_COMMIT();

    float* cur = Bs0;
    float* nxt = Bs1;

    for (int t = 0; t < NPTS / TILE; t++) {
        const int col0 = t * TILE;

        CP_WAIT0();          // B(t) landed
        __syncthreads();     // B(t)+A+lists visible; selection(t-1) done (Ds free)

        if (t + 1 < NPTS / TILE) {
            const int ncol0 = col0 + TILE;
            for (int k = 0; k < 4; k++) {
                const int idx = tid + k * NTHR;
                const int d = idx >> 5, c4 = idx & 31;
                CP_ASYNC16((unsigned)__cvta_generic_to_shared(&nxt[d * BPITCH + 4 * c4]),
                           &g_xT[batch][d][ncol0 + 4 * c4]);
            }
            CP_COMMIT();
        }

        // candidate norms for epilogue (L2-hit LDG, issued early)
        float sb[4];
        #pragma unroll
        for (int n = 0; n < 4; n++) sb[n] = g_nrm[batch][col0 + cbase + 8 * n];

        // ---- GEMM: 128x128x64, M-packed f32x2, 4 pairs x 4 cols ----
        unsigned long long acc2[4][4];
        #pragma unroll
        for (int p = 0; p < 4; p++)
            #pragma unroll
            for (int n = 0; n < 4; n++) acc2[p][n] = 0ull;

        const unsigned long long* aptr = AsP + prbase;   // FIXED (was 4*prbase)
        const float* bptr = cur + cbase;

        #pragma unroll 8
        for (int d = 0; d < DIMS; d++) {
            unsigned long long a2[4], bd[4];
            #pragma unroll
            for (int p = 0; p < 4; p++) a2[p] = aptr[d * APITCH + 4 * p];
            #pragma unroll
            for (int n = 0; n < 4; n++) {
                const float bv = bptr[d * BPITCH + 8 * n];
                asm("mov.b64 %0, {%1, %1};" : "=l"(bd[n]) : "f"(bv));
            }
            #pragma unroll
            for (int p = 0; p < 4; p++)
                #pragma unroll
                for (int n = 0; n < 4; n++) FMA2(acc2[p][n], a2[p], bd[n]);
        }

        // ---- epilogue: dist -> Ds (conflict-free banks at DST=132) ----
        #pragma unroll
        for (int p = 0; p < 4; p++) {
            const int r0 = 2 * (prbase + 4 * p);
            #pragma unroll
            for (int n = 0; n < 4; n++) {
                const int c = cbase + 8 * n;
                float lo, hi;
                asm("mov.b64 {%0, %1}, %2;" : "=f"(lo), "=f"(hi) : "l"(acc2[p][n]));
                Ds[r0 * DST + c]       = (sa0[p] - 2.f * lo) + sb[n];
                Ds[(r0 + 1) * DST + c] = (sa1[p] - 2.f * hi) + sb[n];
            }
        }
        __syncthreads();     // Ds visible

        // ---- selection: ALL 512 threads; thread (srow, sq) scans chunks
        //      c4 = sq + 4*i (ascending col within its sub-list -> stable) ----
        #pragma unroll 4
        for (int i = 0; i < 8; i++) {
            const int c4 = sq + 4 * i;
            float4 dv = *(float4*)&Ds[srow * DST + 4 * c4];
            const float mn = fminf(fminf(dv.x, dv.y), fminf(dv.z, dv.w));
            if (mn < kth) {                          // rare
                #pragma unroll
                for (int e = 0; e < 4; e++) {
                    const float d = (e == 0) ? dv.x : (e == 1) ? dv.y
                                  : (e == 2) ? dv.z : dv.w;
                    if (d < kth) {                   // strict < : stable
                        int j = KNN - 1;
                        while (j > 0 && kds[sbase + j - 1] > d) {
                            kds[sbase + j] = kds[sbase + j - 1];
                            kis[sbase + j] = kis[sbase + j - 1];
                            j--;
                        }
                        kds[sbase + j] = d;
                        kis[sbase + j] = (unsigned short)(col0 + 4 * c4 + e);
                        kth = kds[sbase + KNN - 1];
                    }
                }
            }
        }
        // loop-top barrier separates selection(t) from epilogue(t+1)
        float* tmp = cur; cur = nxt; nxt = tmp;
    }

    __syncthreads();   // all sub-lists final

    // ---- merge 4 sorted sub-lists per row (lexicographic); write output ----
    if (tid < TILE) {
        float* out_nn = out;
        float* out_c  = out + 2 * NPTS * KNN;
        const int grow = row0 + tid;
        const size_t obase = ((size_t)batch * NPTS + grow) * KNN;

        int ptr4[4] = {0, 0, 0, 0};
        #pragma unroll
        for (int j = 0; j < KNN; j++) {
            float best = INF; int bidx = 0x7fffffff; int bl = 0;
            #pragma unroll
            for (int l = 0; l < 4; l++) {
                if (ptr4[l] < KNN) {
                    const int bs = (tid * 4 + l) * KNN + ptr4[l];
                    const float dv = kds[bs];
                    const int   iv = (int)kis[bs];
                    if (dv < best || (dv == best && iv < bidx)) {
                        best = dv; bidx = iv; bl = l;
                    }
                }
            }
            ptr4[bl]++;
            out_nn[obase + j] = (float)bidx;
            out_c [obase + j] = (float)grow;
        }
    }
}

extern "C" void kernel_launch(void* const* d_in, const int* in_sizes, int n_in,
                              void* d_out, int out_size) {
    const float* x = (const float*)d_in[0];
    float* out = (float*)d_out;

    const size_t smem_bytes =
        (size_t)DIMS * APITCH * 8 +              // AsP    33,792
        (size_t)2 * DIMS * BPITCH * 4 +          // Bs0/1  67,584
        (size_t)TILE * DST * 4 +                 // Ds     67,584
        (size_t)TILE * 4 * KNN * 4 +             // kds    32,768
        (size_t)TILE * 4 * KNN * 2;              // kis    16,384  => 218,112

    cudaFuncSetAttribute(knn8,
                         cudaFuncAttributeMaxDynamicSharedMemorySize,
                         (int)smem_bytes);

    dim3 pgrid(NPTS / TILE, 2);
    pre_kernel<<<pgrid, 256>>>(x);

    dim3 grid(NPTS / TILE, 2);
    knn8<<<grid, NTHR, smem_bytes>>>(x, out);
}

// round 14
// speedup vs baseline: 17.5756x; 1.0035x over previous
#include <cuda_runtime.h>

#define KNN 16
#define NPTS 8192
#define DIMS 64
#define TILE 128
#define NTHR 512
#define APITCH 66     // ull per d-row of A: 64 pairs + 2 pad (16B-aligned LDS.128)
#define BPITCH 132    // floats per d-row of B (mult of 4 for cp.async 16B)
#define DST 132       // Ds stride: epilogue banks 8*wy+wx, selection banks 4r+sq - both clean

__device__ float g_xT[2][DIMS][NPTS];   // transposed points
__device__ float g_nrm[2][NPTS];        // squared norms

#define FMA2(acc, a, b) \
    asm("fma.rn.f32x2 %0, %1, %2, %0;" : "+l"(acc) : "l"(a), "l"(b))
#define CP_ASYNC16(smem_u32, gptr) \
    asm volatile("cp.async.ca.shared.global [%0], [%1], 16;" \
                 :: "r"(smem_u32), "l"(gptr))
#define CP_COMMIT()  asm volatile("cp.async.commit_group;")
#define CP_WAIT0()   asm volatile("cp.async.wait_group 0;" ::: "memory")

// ---- pre-kernel: tiled transpose + norms (one-time) ----
__global__ __launch_bounds__(256, 1)
void pre_kernel(const float* __restrict__ x) {
    __shared__ float s[TILE][DIMS + 1];
    const int b = blockIdx.y, n0 = blockIdx.x * TILE, tid = threadIdx.x;
    const float* xb = x + (size_t)b * NPTS * DIMS;

    for (int i = tid; i < TILE * (DIMS / 4); i += 256) {
        const int r = i >> 4, d4 = i & 15;
        float4 v = *(const float4*)&xb[(size_t)(n0 + r) * DIMS + 4 * d4];
        s[r][4 * d4 + 0] = v.x; s[r][4 * d4 + 1] = v.y;
        s[r][4 * d4 + 2] = v.z; s[r][4 * d4 + 3] = v.w;
    }
    __syncthreads();
    if (tid < TILE) {
        float sum = 0.f;
        #pragma unroll
        for (int d = 0; d < DIMS; d++) sum = fmaf(s[tid][d], s[tid][d], sum);
        g_nrm[b][n0 + tid] = sum;
    }
    for (int i = tid; i < DIMS * TILE; i += 256) {
        const int d = i >> 7, c = i & 127;
        g_xT[b][d][n0 + c] = s[c][d];
    }
}

// ---- main kernel: round-9 GEMM + conflict-free parallel selection ----
__global__ __launch_bounds__(NTHR, 1)
void knn9(const float* __restrict__ x, float* __restrict__ out) {
    extern __shared__ unsigned long long smem_u64[];
    unsigned long long* AsP = smem_u64;                    // [64][APITCH] ull
    float* Bs0 = (float*)(AsP + DIMS * APITCH);            // [64][BPITCH]
    float* Bs1 = Bs0 + DIMS * BPITCH;                      // [64][BPITCH]
    float* Ds  = Bs1 + DIMS * BPITCH;                      // [128][DST]
    float* kds = Ds + TILE * DST;                          // [128][4][16]
    unsigned short* kis = (unsigned short*)(kds + TILE * 4 * KNN); // [128][4][16]
    float* AsPf = (float*)AsP;

    const int tid    = threadIdx.x;
    const int lane   = tid & 31;
    const int warp   = tid >> 5;       // 0..15
    const int wy     = lane >> 3;      // 0..3
    const int wx     = lane & 7;       // 0..7
    const int warp_y = warp >> 2;      // 0..3
    const int warp_x = warp & 3;       // 0..3
    const int batch  = blockIdx.y;
    const int row0   = blockIdx.x * TILE;

    const float INF = __int_as_float(0x7f800000);

    // private sub-lists: thread (srow, sq) owns list [srow][sq]
    const int srow = tid >> 2;         // 0..127
    const int sq   = tid & 3;          // 0..3
    const int sbase = (srow * 4 + sq) * KNN;
    #pragma unroll
    for (int j = 0; j < KNN; j++) { kds[sbase + j] = INF; kis[sbase + j] = 0; }
    float kth = INF;

    // A tile: AsPf[d][r] = xT[b][d][row0+r]  (coalesced LDG, conflict-free STS)
    for (int i = tid; i < DIMS * TILE; i += NTHR) {
        const int d = i >> 7, r = i & 127;
        AsPf[d * (2 * APITCH) + r] = g_xT[batch][d][row0 + r];
    }

    const int prbase = 16 * warp_y + wy;   // GEMM row-pairs: prbase + 4*p
    const int cbase  = 32 * warp_x + wx;   // GEMM cols:      cbase + 8*n

    // per-thread GEMM row norms
    float sa0[4], sa1[4];
    #pragma unroll
    for (int p = 0; p < 4; p++) {
        const int r0 = 2 * (prbase + 4 * p);
        sa0[p] = g_nrm[batch][row0 + r0];
        sa1[p] = g_nrm[batch][row0 + r0 + 1];
    }

    // prefetch B(0)
    for (int k = 0; k < 4; k++) {
        const int idx = tid + k * NTHR;          // 64 d x 32 c4
        const int d = idx >> 5, c4 = idx & 31;
        CP_ASYNC16((unsigned)__cvta_generic_to_shared(&Bs0[d * BPITCH + 4 * c4]),
                   &g_xT[batch][d][4 * c4]);
    }
    CP_COMMIT();

    float* cur = Bs0;
    float* nxt = Bs1;

    for (int t = 0; t < NPTS / TILE; t++) {
        const int col0 = t * TILE;

        CP_WAIT0();          // B(t) landed
        __syncthreads();     // B(t)+A+lists visible; selection(t-1) done (Ds free)

        if (t + 1 < NPTS / TILE) {
            const int ncol0 = col0 + TILE;
            for (int k = 0; k < 4; k++) {
                const int idx = tid + k * NTHR;
                const int d = idx >> 5, c4 = idx & 31;
                CP_ASYNC16((unsigned)__cvta_generic_to_shared(&nxt[d * BPITCH + 4 * c4]),
                           &g_xT[batch][d][ncol0 + 4 * c4]);
            }
            CP_COMMIT();
        }

        // candidate norms for epilogue (L2-hit LDG, issued early)
        float sb[4];
        #pragma unroll
        for (int n = 0; n < 4; n++) sb[n] = g_nrm[batch][col0 + cbase + 8 * n];

        // ---- GEMM: 128x128x64, M-packed f32x2, 4 pairs x 4 cols ----
        unsigned long long acc2[4][4];
        #pragma unroll
        for (int p = 0; p < 4; p++)
            #pragma unroll
            for (int n = 0; n < 4; n++) acc2[p][n] = 0ull;

        const unsigned long long* aptr = AsP + prbase;
        const float* bptr = cur + cbase;

        #pragma unroll 8
        for (int d = 0; d < DIMS; d++) {
            unsigned long long a2[4], bd[4];
            #pragma unroll
            for (int p = 0; p < 4; p++) a2[p] = aptr[d * APITCH + 4 * p];
            #pragma unroll
            for (int n = 0; n < 4; n++) {
                const float bv = bptr[d * BPITCH + 8 * n];
                asm("mov.b64 %0, {%1, %1};" : "=l"(bd[n]) : "f"(bv));
            }
            #pragma unroll
            for (int p = 0; p < 4; p++)
                #pragma unroll
                for (int n = 0; n < 4; n++) FMA2(acc2[p][n], a2[p], bd[n]);
        }

        // ---- epilogue: dist -> Ds (banks 8*wy+wx at DST=132 -> clean) ----
        #pragma unroll
        for (int p = 0; p < 4; p++) {
            const int r0 = 2 * (prbase + 4 * p);
            #pragma unroll
            for (int n = 0; n < 4; n++) {
                const int c = cbase + 8 * n;
                float lo, hi;
                asm("mov.b64 {%0, %1}, %2;" : "=f"(lo), "=f"(hi) : "l"(acc2[p][n]));
                Ds[r0 * DST + c]       = (sa0[p] - 2.f * lo) + sb[n];
                Ds[(r0 + 1) * DST + c] = (sa1[p] - 2.f * hi) + sb[n];
            }
        }
        __syncthreads();     // Ds visible

        // ---- selection: thread (srow, sq) scans cols sq+4c, c=0..31, as
        //      SCALAR LDS.32: banks = 4*(lane>>2) + (lane&3) + const -> a
        //      perfect 0..31 permutation, zero conflicts. Ascending col order
        //      within each sub-list -> strict < insert stays stable. ----
        {
            const float* dsr = &Ds[srow * DST + sq];
            #pragma unroll 2
            for (int g = 0; g < 8; g++) {
                const float d0 = dsr[16 * g];          // col sq + 16g
                const float d1 = dsr[16 * g + 4];      // col sq + 16g + 4
                const float d2 = dsr[16 * g + 8];
                const float d3 = dsr[16 * g + 12];
                const float mn = fminf(fminf(d0, d1), fminf(d2, d3));
                if (mn < kth) {                        // rare
                    #pragma unroll
                    for (int u = 0; u < 4; u++) {
                        const float d = (u == 0) ? d0 : (u == 1) ? d1
                                      : (u == 2) ? d2 : d3;
                        if (d < kth) {
                            int j = KNN - 1;
                            while (j > 0 && kds[sbase + j - 1] > d) {
                                kds[sbase + j] = kds[sbase + j - 1];
                                kis[sbase + j] = kis[sbase + j - 1];
                                j--;
                            }
                            kds[sbase + j] = d;
                            kis[sbase + j] =
                                (unsigned short)(col0 + sq + 16 * g + 4 * u);
                            kth = kds[sbase + KNN - 1];
                        }
                    }
                }
            }
        }
        // loop-top barrier separates selection(t) from epilogue(t+1)
        float* tmp = cur; cur = nxt; nxt = tmp;
    }

    __syncthreads();   // all sub-lists final

    // ---- merge 4 sorted sub-lists per row (lexicographic); write output ----
    if (tid < TILE) {
        float* out_nn = out;
        float* out_c  = out + 2 * NPTS * KNN;
        const int grow = row0 + tid;
        const size_t obase = ((size_t)batch * NPTS + grow) * KNN;

        int ptr4[4] = {0, 0, 0, 0};
        #pragma unroll
        for (int j = 0; j < KNN; j++) {
            float best = INF; int bidx = 0x7fffffff; int bl = 0;
            #pragma unroll
            for (int l = 0; l < 4; l++) {
                if (ptr4[l] < KNN) {
                    const int bs = (tid * 4 + l) * KNN + ptr4[l];
                    const float dv = kds[bs];
                    const int   iv = (int)kis[bs];
                    if (dv < best || (dv == best && iv < bidx)) {
                        best = dv; bidx = iv; bl = l;
                    }
                }
            }
            ptr4[bl]++;
            out_nn[obase + j] = (float)bidx;
            out_c [obase + j] = (float)grow;
        }
    }
}

extern "C" void kernel_launch(void* const* d_in, const int* in_sizes, int n_in,
                              void* d_out, int out_size) {
    const float* x = (const float*)d_in[0];
    float* out = (float*)d_out;

    const size_t smem_bytes =
        (size_t)DIMS * APITCH * 8 +              // AsP    33,792
        (size_t)2 * DIMS * BPITCH * 4 +          // Bs0/1  67,584
        (size_t)TILE * DST * 4 +                 // Ds     67,584
        (size_t)TILE * 4 * KNN * 4 +             // kds    32,768
        (size_t)TILE * 4 * KNN * 2;              // kis    16,384  => 218,112

    cudaFuncSetAttribute(knn9,
                         cudaFuncAttributeMaxDynamicSharedMemorySize,
                         (int)smem_bytes);

    dim3 pgrid(NPTS / TILE, 2);
    pre_kernel<<<pgrid, 256>>>(x);

    dim3 grid(NPTS / TILE, 2);
    knn9<<<grid, NTHR, smem_bytes>>>(x, out);
}